// round 5
// baseline (speedup 1.0000x reference)
#include <cuda_runtime.h>
#include <math.h>

// Problem constants
#define B_    2
#define S_    2048
#define D_    1024
#define E_    1024
#define H_    16
#define DH_   64
#define E3_   3072
#define MTOT  (B_ * S_)   // 4096

// Scratch (alloc-free: __device__ globals)
__device__ float g_qkv[(size_t)MTOT * E3_];   // 4096 x 3072  (50.3 MB)
__device__ float g_att[(size_t)MTOT * E_];    // 4096 x 1024  (16.8 MB)

// ---------------------------------------------------------------------------
// SGEMM: C[M,N] = A[M,K] @ W[N,K]^T + bias[N]
// 128x128 block tile, BK=16, 256 threads, 8x8 per-thread micro-tile.
// A and W are both K-major (row-major with K contiguous).
// ---------------------------------------------------------------------------
#define BM 128
#define BN 128
#define BK 16
#define SMS 132   // padded smem row stride (multiple of 4 -> float4-aligned)

__global__ __launch_bounds__(256) void sgemm_bias(
    const float* __restrict__ A, const float* __restrict__ W,
    const float* __restrict__ bias, float* __restrict__ C,
    int M, int N, int K)
{
    __shared__ float As[BK][SMS];
    __shared__ float Bs[BK][SMS];

    const int tid = threadIdx.x;
    const int ty = tid >> 4;        // 0..15
    const int tx = tid & 15;        // 0..15
    const int bm = blockIdx.y * BM;
    const int bn = blockIdx.x * BN;

    float acc[8][8];
#pragma unroll
    for (int i = 0; i < 8; i++)
#pragma unroll
        for (int j = 0; j < 8; j++) acc[i][j] = 0.0f;

    for (int k0 = 0; k0 < K; k0 += BK) {
        // Load A,B tiles: 512 float4 each, 2 per thread, transposed into smem.
#pragma unroll
        for (int i = 0; i < 2; i++) {
            int idx = tid + i * 256;          // 0..511
            int row = idx >> 2;               // 0..127
            int kc  = (idx & 3) * 4;          // 0,4,8,12
            float4 a = *(const float4*)(A + (size_t)(bm + row) * K + k0 + kc);
            As[kc + 0][row] = a.x;
            As[kc + 1][row] = a.y;
            As[kc + 2][row] = a.z;
            As[kc + 3][row] = a.w;
            float4 b = *(const float4*)(W + (size_t)(bn + row) * K + k0 + kc);
            Bs[kc + 0][row] = b.x;
            Bs[kc + 1][row] = b.y;
            Bs[kc + 2][row] = b.z;
            Bs[kc + 3][row] = b.w;
        }
        __syncthreads();

#pragma unroll
        for (int k = 0; k < BK; k++) {
            float4 a0 = *(const float4*)&As[k][ty * 4];
            float4 a1 = *(const float4*)&As[k][64 + ty * 4];
            float4 b0 = *(const float4*)&Bs[k][tx * 4];
            float4 b1 = *(const float4*)&Bs[k][64 + tx * 4];
            float av[8] = {a0.x, a0.y, a0.z, a0.w, a1.x, a1.y, a1.z, a1.w};
            float bv[8] = {b0.x, b0.y, b0.z, b0.w, b1.x, b1.y, b1.z, b1.w};
#pragma unroll
            for (int i = 0; i < 8; i++)
#pragma unroll
                for (int j = 0; j < 8; j++)
                    acc[i][j] += av[i] * bv[j];
        }
        __syncthreads();
    }

    // Epilogue: rows {ty*4+il, 64+ty*4+il}, cols {tx*4+j, 64+tx*4+j}
#pragma unroll
    for (int ih = 0; ih < 2; ih++) {
#pragma unroll
        for (int il = 0; il < 4; il++) {
            int r  = bm + ih * 64 + ty * 4 + il;
            int ai = ih * 4 + il;
#pragma unroll
            for (int jh = 0; jh < 2; jh++) {
                int c = bn + jh * 64 + tx * 4;
                float4 o;
                o.x = acc[ai][jh * 4 + 0] + bias[c + 0];
                o.y = acc[ai][jh * 4 + 1] + bias[c + 1];
                o.z = acc[ai][jh * 4 + 2] + bias[c + 2];
                o.w = acc[ai][jh * 4 + 3] + bias[c + 3];
                *(float4*)(C + (size_t)r * N + c) = o;
            }
        }
    }
}

// ---------------------------------------------------------------------------
// Flash attention (fp32). One block = one (b,h) x 64-query tile.
// qkv layout per row (3072): channel = h*192 + {q:0..63, k:64..127, v:128..191}
// Smem: Qs[d][r] (scaled), KP[.][.] holds K as [d][kc] then P as [r][kc],
// Vs[kc][vd]. 48 KB total. Per-thread 4x4 fragments, online softmax with
// 16-lane shuffle reductions (all 16 tx lanes of a row group are a half-warp).
// ---------------------------------------------------------------------------
__global__ __launch_bounds__(256) void attn_kernel(
    const float* __restrict__ qkv, float* __restrict__ outp)
{
    __shared__ float Qs[64][64];   // [d][r]
    __shared__ float KP[64][64];   // K: [d][kc]  ->  P: [r][kc]
    __shared__ float Vs[64][64];   // [kc][vd]

    const int tid = threadIdx.x;
    const int ty = tid >> 4;       // 0..15 -> rows 4ty..4ty+3
    const int tx = tid & 15;       // 0..15 -> cols 4tx..4tx+3
    const int qbase = blockIdx.x * 64;
    const int b = blockIdx.y >> 4;
    const int h = blockIdx.y & 15;
    const size_t hoff = (size_t)h * 192;

    // Load Q transposed ([d][r]) and pre-scaled by Dh^-0.5 = 0.125.
    // Mapping r = idx&63 keeps the transposed STS conflict-free (bank = r).
#pragma unroll
    for (int i = 0; i < 4; i++) {
        int idx = tid + i * 256;       // 0..1023
        int r   = idx & 63;
        int d4  = (idx >> 6) << 2;     // 0..60
        float4 v = *(const float4*)(qkv + (size_t)(b * S_ + qbase + r) * E3_ + hoff + d4);
        Qs[d4 + 0][r] = v.x * 0.125f;
        Qs[d4 + 1][r] = v.y * 0.125f;
        Qs[d4 + 2][r] = v.z * 0.125f;
        Qs[d4 + 3][r] = v.w * 0.125f;
    }

    float m[4], l[4], O[4][4];
#pragma unroll
    for (int i = 0; i < 4; i++) {
        m[i] = -1e30f;
        l[i] = 0.0f;
#pragma unroll
        for (int j = 0; j < 4; j++) O[i][j] = 0.0f;
    }

    for (int t = 0; t < S_ / 64; t++) {
        const int kb = t * 64;
        // K tile, transposed [d][kc] (conflict-free STS via r = idx&63)
#pragma unroll
        for (int i = 0; i < 4; i++) {
            int idx = tid + i * 256;
            int r   = idx & 63;
            int d4  = (idx >> 6) << 2;
            float4 kv = *(const float4*)(qkv + (size_t)(b * S_ + kb + r) * E3_ + hoff + 64 + d4);
            KP[d4 + 0][r] = kv.x;
            KP[d4 + 1][r] = kv.y;
            KP[d4 + 2][r] = kv.z;
            KP[d4 + 3][r] = kv.w;
        }
        // V tile, natural [kc][vd] (coalesced load, float4 store)
#pragma unroll
        for (int i = 0; i < 4; i++) {
            int idx = tid + i * 256;
            int r   = idx >> 4;
            int d4  = (idx & 15) << 2;
            float4 vv = *(const float4*)(qkv + (size_t)(b * S_ + kb + r) * E3_ + hoff + 128 + d4);
            *(float4*)&Vs[r][d4] = vv;
        }
        __syncthreads();

        // S = Q @ K^T : 64x64, per-thread 4x4
        float Sc[4][4];
#pragma unroll
        for (int i = 0; i < 4; i++)
#pragma unroll
            for (int j = 0; j < 4; j++) Sc[i][j] = 0.0f;

#pragma unroll 16
        for (int d = 0; d < 64; d++) {
            float4 qa = *(const float4*)&Qs[d][ty * 4];
            float4 kk = *(const float4*)&KP[d][tx * 4];
            float av[4] = {qa.x, qa.y, qa.z, qa.w};
            float bv[4] = {kk.x, kk.y, kk.z, kk.w};
#pragma unroll
            for (int i = 0; i < 4; i++)
#pragma unroll
                for (int j = 0; j < 4; j++)
                    Sc[i][j] += av[i] * bv[j];
        }

        // Online softmax. Row r is owned by the 16 tx-lanes of one half-warp.
        float rmax[4];
#pragma unroll
        for (int i = 0; i < 4; i++)
            rmax[i] = fmaxf(fmaxf(Sc[i][0], Sc[i][1]), fmaxf(Sc[i][2], Sc[i][3]));
#pragma unroll
        for (int o = 1; o < 16; o <<= 1) {
#pragma unroll
            for (int i = 0; i < 4; i++)
                rmax[i] = fmaxf(rmax[i], __shfl_xor_sync(0xffffffffu, rmax[i], o));
        }

        float sc[4];
#pragma unroll
        for (int i = 0; i < 4; i++) {
            float nm = fmaxf(m[i], rmax[i]);
            sc[i] = __expf(m[i] - nm);
            m[i] = nm;
        }

        float rs[4];
#pragma unroll
        for (int i = 0; i < 4; i++) {
#pragma unroll
            for (int j = 0; j < 4; j++)
                Sc[i][j] = __expf(Sc[i][j] - m[i]);
            rs[i] = (Sc[i][0] + Sc[i][1]) + (Sc[i][2] + Sc[i][3]);
        }
#pragma unroll
        for (int o = 1; o < 16; o <<= 1) {
#pragma unroll
            for (int i = 0; i < 4; i++)
                rs[i] += __shfl_xor_sync(0xffffffffu, rs[i], o);
        }
#pragma unroll
        for (int i = 0; i < 4; i++) {
            l[i] = l[i] * sc[i] + rs[i];
#pragma unroll
            for (int j = 0; j < 4; j++) O[i][j] *= sc[i];
        }

        __syncthreads();   // everyone done reading KP as K
        // Store P into KP as [r][kc]
#pragma unroll
        for (int i = 0; i < 4; i++) {
            float4 p = make_float4(Sc[i][0], Sc[i][1], Sc[i][2], Sc[i][3]);
            *(float4*)&KP[ty * 4 + i][tx * 4] = p;
        }
        __syncthreads();

        // O += P @ V : rows = P rows, cols = V dims
#pragma unroll 16
        for (int kc = 0; kc < 64; kc++) {
            float4 vb = *(const float4*)&Vs[kc][tx * 4];
            float p0 = KP[ty * 4 + 0][kc];
            float p1 = KP[ty * 4 + 1][kc];
            float p2 = KP[ty * 4 + 2][kc];
            float p3 = KP[ty * 4 + 3][kc];
            O[0][0] += p0 * vb.x; O[0][1] += p0 * vb.y; O[0][2] += p0 * vb.z; O[0][3] += p0 * vb.w;
            O[1][0] += p1 * vb.x; O[1][1] += p1 * vb.y; O[1][2] += p1 * vb.z; O[1][3] += p1 * vb.w;
            O[2][0] += p2 * vb.x; O[2][1] += p2 * vb.y; O[2][2] += p2 * vb.z; O[2][3] += p2 * vb.w;
            O[3][0] += p3 * vb.x; O[3][1] += p3 * vb.y; O[3][2] += p3 * vb.z; O[3][3] += p3 * vb.w;
        }
        __syncthreads();
    }

    // Finalize: divide by l, write [B,S,E] with e = h*64 + vd
#pragma unroll
    for (int i = 0; i < 4; i++) {
        float inv = 1.0f / l[i];
        int r = qbase + ty * 4 + i;
        float4 o = make_float4(O[i][0] * inv, O[i][1] * inv, O[i][2] * inv, O[i][3] * inv);
        *(float4*)(outp + (size_t)(b * S_ + r) * E_ + h * 64 + tx * 4) = o;
    }
}

// ---------------------------------------------------------------------------
// Launch
// ---------------------------------------------------------------------------
extern "C" void kernel_launch(void* const* d_in, const int* in_sizes, int n_in,
                              void* d_out, int out_size)
{
    const float* x     = (const float*)d_in[0];
    const float* qkv_w = (const float*)d_in[1];
    const float* qkv_b = (const float*)d_in[2];
    const float* o_w   = (const float*)d_in[3];
    const float* o_b   = (const float*)d_in[4];
    float* out = (float*)d_out;

    // Resolve scratch symbol addresses once (first call is the un-captured
    // correctness run, so the capture call performs no runtime API lookups).
    static float* qkv_buf = nullptr;
    static float* att_buf = nullptr;
    if (!qkv_buf) {
        cudaGetSymbolAddress((void**)&qkv_buf, g_qkv);
        cudaGetSymbolAddress((void**)&att_buf, g_att);
    }

    // 1) QKV projection: [4096,1024] @ [3072,1024]^T + b -> [4096,3072]
    dim3 g1(E3_ / BN, MTOT / BM);
    sgemm_bias<<<g1, 256>>>(x, qkv_w, qkv_b, qkv_buf, MTOT, E3_, D_);

    // 2) Attention: 32 q-tiles x 32 (b,h)
    dim3 g2(S_ / 64, B_ * H_);
    attn_kernel<<<g2, 256>>>(qkv_buf, att_buf);

    // 3) Output projection: [4096,1024] @ [1024,1024]^T + b -> [4096,1024]
    dim3 g3(E_ / BN, MTOT / BM);
    sgemm_bias<<<g3, 256>>>(att_buf, o_w, o_b, out, MTOT, E_, D_);
}